// round 2
// baseline (speedup 1.0000x reference)
#include <cuda_runtime.h>
#include <math.h>

#define B_ROWS 16384
#define IN1    256
#define HD     512
#define NB     16
#define NPART  128   // partial-sum blocks for stats

typedef unsigned long long u64;

// ---------------- scratch (device globals: no allocations allowed) ----------
__device__ float  g_mu1[IN1], g_inv1[IN1];
__device__ float  g_mu2[HD],  g_inv2[HD];
__device__ float  g_mu3[HD],  g_inv3[HD];
__device__ float  g_ps[NPART * HD];
__device__ float  g_pq[NPART * HD];
__device__ float2 g_tr1[B_ROWS * IN1];          // (t, r) for layer 1 input
__device__ float2 g_tr2[B_ROWS * HD];           // (t, r) for layer 2 / reused for layer 3
__device__ float  g_h1[B_ROWS * HD];
__device__ float  g_h2[B_ROWS * HD];
__device__ float  g_cp1[IN1 * NB * HD];         // transformed coeffs, layout [i][j][O]
__device__ float  g_cp2[HD * NB * HD];
__device__ float  g_cp3[HD * NB];

// ---------------- packed f32x2 helpers --------------------------------------
__device__ __forceinline__ u64 pk2(float lo, float hi) {
    u64 d; asm("mov.b64 %0, {%1, %2};" : "=l"(d) : "f"(lo), "f"(hi)); return d;
}
__device__ __forceinline__ void upk2(u64 v, float &lo, float &hi) {
    asm("mov.b64 {%0, %1}, %2;" : "=f"(lo), "=f"(hi) : "l"(v));
}
__device__ __forceinline__ u64 ffma2(u64 a, u64 b, u64 c) {
    u64 d; asm("fma.rn.f32x2 %0, %1, %2, %3;" : "=l"(d) : "l"(a), "l"(b), "l"(c));
    return d;
}

// ---------------- stats: per-column mean / unbiased std ---------------------
// Pass 1: each of NPART blocks reduces B_ROWS/NPART rows (deterministic).
__global__ void k_stats_part(const float* __restrict__ src, int C) {
    const int rows = B_ROWS / NPART;
    const int r0 = blockIdx.x * rows;
    float s[2] = {0.f, 0.f}, q[2] = {0.f, 0.f};
    const int ncc = C >> 8;   // C is 256 or 512, blockDim = 256
    for (int rr = 0; rr < rows; rr++) {
        const float* row = src + (size_t)(r0 + rr) * C;
        for (int cc = 0; cc < ncc; cc++) {
            float v = row[threadIdx.x + (cc << 8)];
            s[cc] += v;
            q[cc] = fmaf(v, v, q[cc]);
        }
    }
    for (int cc = 0; cc < ncc; cc++) {
        g_ps[blockIdx.x * C + threadIdx.x + (cc << 8)] = s[cc];
        g_pq[blockIdx.x * C + threadIdx.x + (cc << 8)] = q[cc];
    }
}

// Pass 2: finalize mu and 1/(sd+1e-6)
__global__ void k_stats_fin(int C, float* __restrict__ mu, float* __restrict__ inv) {
    int c = blockIdx.x * blockDim.x + threadIdx.x;
    if (c >= C) return;
    float s = 0.f, q = 0.f;
    for (int k = 0; k < NPART; k++) { s += g_ps[k * C + c]; q += g_pq[k * C + c]; }
    float m = s / (float)B_ROWS;
    float var = (q - s * m) / (float)(B_ROWS - 1);
    float sd = sqrtf(fmaxf(var, 0.f));
    mu[c] = m;
    inv[c] = 1.f / (sd + 1e-6f);
}

// ---------------- (t, r) precompute ------------------------------------------
// xn = clip((v-mu)*inv, -3, 3); t = exp(-2xn^2-8xn); r = exp(16xn/15)
__global__ void k_prep_tr(const float* __restrict__ src,
                          const float* __restrict__ mu,
                          const float* __restrict__ inv,
                          int cmask, int total, float2* __restrict__ dst) {
    for (int idx = blockIdx.x * blockDim.x + threadIdx.x; idx < total;
         idx += gridDim.x * blockDim.x) {
        int c = idx & cmask;
        float xn = (src[idx] - mu[c]) * inv[c];
        xn = fminf(3.f, fmaxf(-3.f, xn));
        float t = __expf(fmaf(-2.f * xn, xn, -8.f * xn));
        float r = __expf(xn * (16.f / 15.f));
        dst[idx] = make_float2(t, r);
    }
}

// ---------------- coefficient transform --------------------------------------
// dst[(i*16+j)*O + o] = src[(o*IN+i)*16 + n] * Kn, with n = 15-j (Horner order)
__global__ void k_prep_coeffs(const float* __restrict__ src, int O, int IN_,
                              float* __restrict__ dst) {
    int i = blockIdx.x;
    for (int w = threadIdx.x; w < NB * O; w += blockDim.x) {
        int o = w % O;
        int j = w / O;
        int n = 15 - j;
        float cn = fmaf((float)n, 4.f / 15.f, -2.f);
        float K = expf(-2.f * cn * cn);
        dst[(size_t)(i * NB + j) * O + o] = src[((size_t)o * IN_ + i) * NB + n] * K;
    }
}

// ---------------- main Horner-GEMM layer -------------------------------------
// out[b,o] = (tanh of) sum_i t[b,i] * P_{o,i}(r[b,i]),  P = 15-step Horner
// Tiles: BM=64 rows, BN=64 cols, BI=8 inputs/step. 128 threads, 4x8 per thread.
template <bool TANH>
__global__ void __launch_bounds__(128)
k_layer(const float2* __restrict__ tr, const float* __restrict__ cp,
        float* __restrict__ out, int IN_, int O) {
    __shared__ float2 s_tr[8][64];
    __shared__ __align__(16) float s_cp[8][16][64];

    const int tid = threadIdx.x;
    const int tx = tid & 15;      // row group (4 rows each)
    const int ty = tid >> 4;      // col group (8 cols each)
    const int bm0 = blockIdx.y * 64;
    const int on0 = blockIdx.x * 64;

    u64 acc[4][4];
#pragma unroll
    for (int mm = 0; mm < 4; mm++)
#pragma unroll
        for (int g = 0; g < 4; g++) acc[mm][g] = 0ull;

    for (int i0 = 0; i0 < IN_; i0 += 8) {
        // load (t,r) tile: 512 float2
#pragma unroll
        for (int k = 0; k < 4; k++) {
            int e = tid + 128 * k;
            int il = e & 7, m = e >> 3;
            s_tr[il][m] = tr[(size_t)(bm0 + m) * IN_ + i0 + il];
        }
        // load coeff tile: [8][16][64] floats as float4
#pragma unroll
        for (int k = 0; k < 16; k++) {
            int f = tid + 128 * k;
            int il = f >> 8, rest = f & 255;
            int j = rest >> 4, g4 = rest & 15;
            const float4* s =
                reinterpret_cast<const float4*>(cp + (size_t)((i0 + il) * NB + j) * O + on0);
            reinterpret_cast<float4*>(&s_cp[il][j][0])[g4] = s[g4];
        }
        __syncthreads();

#pragma unroll
        for (int il = 0; il < 8; il++) {
            u64 t2[4], r2[4];
#pragma unroll
            for (int mm = 0; mm < 4; mm++) {
                float2 v = s_tr[il][tx * 4 + mm];
                t2[mm] = pk2(v.x, v.x);
                r2[mm] = pk2(v.y, v.y);
            }
            u64 p[4][4];
            {
                float4 c0 = *reinterpret_cast<const float4*>(&s_cp[il][0][ty * 8]);
                float4 c1 = *reinterpret_cast<const float4*>(&s_cp[il][0][ty * 8 + 4]);
                u64 cA = pk2(c0.x, c0.y), cB = pk2(c0.z, c0.w);
                u64 cC = pk2(c1.x, c1.y), cD = pk2(c1.z, c1.w);
#pragma unroll
                for (int mm = 0; mm < 4; mm++) {
                    p[mm][0] = cA; p[mm][1] = cB; p[mm][2] = cC; p[mm][3] = cD;
                }
            }
#pragma unroll
            for (int j = 1; j < 16; j++) {
                float4 c0 = *reinterpret_cast<const float4*>(&s_cp[il][j][ty * 8]);
                float4 c1 = *reinterpret_cast<const float4*>(&s_cp[il][j][ty * 8 + 4]);
                u64 cc[4] = {pk2(c0.x, c0.y), pk2(c0.z, c0.w),
                             pk2(c1.x, c1.y), pk2(c1.z, c1.w)};
#pragma unroll
                for (int mm = 0; mm < 4; mm++)
#pragma unroll
                    for (int g = 0; g < 4; g++)
                        p[mm][g] = ffma2(p[mm][g], r2[mm], cc[g]);
            }
#pragma unroll
            for (int mm = 0; mm < 4; mm++)
#pragma unroll
                for (int g = 0; g < 4; g++)
                    acc[mm][g] = ffma2(t2[mm], p[mm][g], acc[mm][g]);
        }
        __syncthreads();
    }

#pragma unroll
    for (int mm = 0; mm < 4; mm++) {
        int row = bm0 + tx * 4 + mm;
        float v[8];
#pragma unroll
        for (int g = 0; g < 4; g++) upk2(acc[mm][g], v[2 * g], v[2 * g + 1]);
        if (TANH) {
#pragma unroll
            for (int k = 0; k < 8; k++) v[k] = tanhf(v[k]);
        }
        float4 w0 = make_float4(v[0], v[1], v[2], v[3]);
        float4 w1 = make_float4(v[4], v[5], v[6], v[7]);
        float4* dst = reinterpret_cast<float4*>(out + (size_t)row * O + on0 + ty * 8);
        dst[0] = w0;
        dst[1] = w1;
    }
}

// ---------------- layer 3 (O=1) + skip ---------------------------------------
__global__ void k_final(const float2* __restrict__ tr, const float* __restrict__ cp3,
                        const float* __restrict__ x, const float* __restrict__ sw,
                        const float* __restrict__ sb, float* __restrict__ out) {
    int warp = threadIdx.x >> 5, lane = threadIdx.x & 31;
    int b = blockIdx.x * 8 + warp;
    float acc = 0.f;
    for (int i = lane; i < HD; i += 32) {
        float2 v = tr[(size_t)b * HD + i];
        const float* c = &cp3[i * NB];
        float p = c[0];
#pragma unroll
        for (int j = 1; j < NB; j++) p = fmaf(p, v.y, c[j]);
        acc = fmaf(v.x, p, acc);
    }
    for (int cidx = lane; cidx < IN1; cidx += 32)
        acc = fmaf(x[(size_t)b * IN1 + cidx], sw[cidx], acc);
#pragma unroll
    for (int off = 16; off; off >>= 1) acc += __shfl_xor_sync(0xffffffffu, acc, off);
    if (lane == 0) out[b] = acc + sb[0];
}

// ---------------- launch -----------------------------------------------------
extern "C" void kernel_launch(void* const* d_in, const int* in_sizes, int n_in,
                              void* d_out, int out_size) {
    const float* x  = (const float*)d_in[0];
    const float* c1 = (const float*)d_in[1];
    const float* c2 = (const float*)d_in[2];
    const float* c3 = (const float*)d_in[3];
    const float* sw = (const float*)d_in[4];
    const float* sb = (const float*)d_in[5];
    float* out = (float*)d_out;

    float2 *tr1, *tr2;
    float *h1, *h2, *cp1, *cp2, *cp3;
    float *mu1, *inv1, *mu2, *inv2, *mu3, *inv3;
    cudaGetSymbolAddress((void**)&tr1,  g_tr1);
    cudaGetSymbolAddress((void**)&tr2,  g_tr2);
    cudaGetSymbolAddress((void**)&h1,   g_h1);
    cudaGetSymbolAddress((void**)&h2,   g_h2);
    cudaGetSymbolAddress((void**)&cp1,  g_cp1);
    cudaGetSymbolAddress((void**)&cp2,  g_cp2);
    cudaGetSymbolAddress((void**)&cp3,  g_cp3);
    cudaGetSymbolAddress((void**)&mu1,  g_mu1);
    cudaGetSymbolAddress((void**)&inv1, g_inv1);
    cudaGetSymbolAddress((void**)&mu2,  g_mu2);
    cudaGetSymbolAddress((void**)&inv2, g_inv2);
    cudaGetSymbolAddress((void**)&mu3,  g_mu3);
    cudaGetSymbolAddress((void**)&inv3, g_inv3);

    // coefficient transforms (cheap, every call: deterministic)
    k_prep_coeffs<<<IN1, 256>>>(c1, HD, IN1, cp1);
    k_prep_coeffs<<<HD,  256>>>(c2, HD, HD,  cp2);
    k_prep_coeffs<<<HD,  256>>>(c3, 1,  HD,  cp3);

    // layer 1
    k_stats_part<<<NPART, 256>>>(x, IN1);
    k_stats_fin<<<1, 256>>>(IN1, mu1, inv1);
    k_prep_tr<<<2048, 256>>>(x, mu1, inv1, IN1 - 1, B_ROWS * IN1, tr1);
    k_layer<true><<<dim3(HD / 64, B_ROWS / 64), 128>>>(tr1, cp1, h1, IN1, HD);

    // layer 2
    k_stats_part<<<NPART, 256>>>(h1, HD);
    k_stats_fin<<<2, 256>>>(HD, mu2, inv2);
    k_prep_tr<<<4096, 256>>>(h1, mu2, inv2, HD - 1, B_ROWS * HD, tr2);
    k_layer<true><<<dim3(HD / 64, B_ROWS / 64), 128>>>(tr2, cp2, h2, HD, HD);

    // layer 3 + skip
    k_stats_part<<<NPART, 256>>>(h2, HD);
    k_stats_fin<<<2, 256>>>(HD, mu3, inv3);
    k_prep_tr<<<4096, 256>>>(h2, mu3, inv3, HD - 1, B_ROWS * HD, tr2);  // reuse tr2
    k_final<<<B_ROWS / 8, 256>>>(tr2, cp3, x, sw, sb, out);
}

// round 5
// speedup vs baseline: 1.9714x; 1.9714x over previous
#include <cuda_runtime.h>
#include <cuda_bf16.h>
#include <math.h>
#include <stdint.h>

#define B_ROWS 16384
#define IN1    256
#define HD     512
#define NB     16
#define NPART  512
#define K1     (IN1 * NB)   // 4096
#define K2     (HD * NB)    // 8192

// GEMM tiling
#define BM 128
#define BN 128
#define BK 64
#define NSTAGE 3
#define ST_AH 0
#define ST_AL 16384
#define ST_BH 32768
#define ST_BL 49152
#define STAGE_BYTES 65536
#define GEMM_SMEM (NSTAGE * STAGE_BYTES)

// ---------------- scratch (device globals) -----------------------------------
__device__ float g_mu1[IN1], g_inv1[IN1];
__device__ float g_mu2[HD],  g_inv2[HD];
__device__ float g_mu3[HD],  g_inv3[HD];
__device__ float g_ps[NPART * HD];
__device__ float g_pq[NPART * HD];
__device__ __align__(128) __nv_bfloat16 g_Ah[(size_t)B_ROWS * K2];
__device__ __align__(128) __nv_bfloat16 g_Al[(size_t)B_ROWS * K2];
__device__ __align__(128) __nv_bfloat16 g_cb1h[(size_t)HD * K1];
__device__ __align__(128) __nv_bfloat16 g_cb1l[(size_t)HD * K1];
__device__ __align__(128) __nv_bfloat16 g_cb2h[(size_t)HD * K2];
__device__ __align__(128) __nv_bfloat16 g_cb2l[(size_t)HD * K2];
__device__ float  g_h1[(size_t)B_ROWS * HD];
__device__ float  g_h2[(size_t)B_ROWS * HD];
__device__ float  g_cp3[HD * NB];
__device__ float2 g_tr[(size_t)B_ROWS * HD];

// ---------------- PTX helpers --------------------------------------------------
__device__ __forceinline__ uint32_t smem_u32(const void* p) {
    uint32_t a;
    asm("{ .reg .u64 t; cvta.to.shared.u64 t, %1; cvt.u32.u64 %0, t; }" : "=r"(a) : "l"(p));
    return a;
}
__device__ __forceinline__ uint32_t sw128(uint32_t b) { return b ^ ((b >> 3) & 0x70u); }
__device__ __forceinline__ void cp16(uint32_t s, const void* g) {
    asm volatile("cp.async.cg.shared.global [%0], [%1], 16;" :: "r"(s), "l"(g));
}
#define CP_COMMIT() asm volatile("cp.async.commit_group;" ::: "memory")

__device__ __forceinline__ void ldmx4(uint32_t* r, uint32_t addr) {
    asm volatile("ldmatrix.sync.aligned.m8n8.x4.shared.b16 {%0,%1,%2,%3}, [%4];"
        : "=r"(r[0]), "=r"(r[1]), "=r"(r[2]), "=r"(r[3]) : "r"(addr));
}
__device__ __forceinline__ void mma16816(float* c, const uint32_t* a, const uint32_t* b) {
    asm volatile("mma.sync.aligned.m16n8k16.row.col.f32.bf16.bf16.f32 "
        "{%0,%1,%2,%3}, {%4,%5,%6,%7}, {%8,%9}, {%0,%1,%2,%3};"
        : "+f"(c[0]), "+f"(c[1]), "+f"(c[2]), "+f"(c[3])
        : "r"(a[0]), "r"(a[1]), "r"(a[2]), "r"(a[3]), "r"(b[0]), "r"(b[1]));
}

// ---------------- stats --------------------------------------------------------
__global__ void k_stats_part(const float* __restrict__ src, int C) {
    const int rows = B_ROWS / NPART;   // 32
    const int r0 = blockIdx.x * rows;
    float s[2] = {0.f, 0.f}, q[2] = {0.f, 0.f};
    const int ncc = C >> 8;
    for (int rr = 0; rr < rows; rr++) {
        const float* row = src + (size_t)(r0 + rr) * C;
        for (int cc = 0; cc < ncc; cc++) {
            float v = row[threadIdx.x + (cc << 8)];
            s[cc] += v;
            q[cc] = fmaf(v, v, q[cc]);
        }
    }
    for (int cc = 0; cc < ncc; cc++) {
        g_ps[blockIdx.x * C + threadIdx.x + (cc << 8)] = s[cc];
        g_pq[blockIdx.x * C + threadIdx.x + (cc << 8)] = q[cc];
    }
}

__global__ void k_stats_fin(int C, float* __restrict__ mu, float* __restrict__ inv) {
    int c = blockIdx.x * blockDim.x + threadIdx.x;
    if (c >= C) return;
    float s = 0.f, q = 0.f;
    for (int k = 0; k < NPART; k++) { s += g_ps[k * C + c]; q += g_pq[k * C + c]; }
    float m = s / (float)B_ROWS;
    float var = (q - s * m) / (float)(B_ROWS - 1);
    float sd = sqrtf(fmaxf(var, 0.f));
    mu[c] = m;
    inv[c] = 1.f / (sd + 1e-6f);
}

// ---------------- basis materialization (bf16 hi/lo, Kn excluded) --------------
__global__ void k_basis(const float* __restrict__ src, const float* __restrict__ mu,
                        const float* __restrict__ inv, int cmask,
                        __nv_bfloat16* __restrict__ Ah, __nv_bfloat16* __restrict__ Al) {
    int idx = blockIdx.x * blockDim.x + threadIdx.x;   // one per (b, i)
    int i = idx & cmask;
    float xn = (src[idx] - mu[i]) * inv[i];
    xn = fminf(3.f, fmaxf(-3.f, xn));
    float t = __expf(fmaf(-2.f * xn, xn, -8.f * xn));
    float r = __expf(xn * (16.f / 15.f));
    unsigned hh[8], ll[8];
    float pv = t;
#pragma unroll
    for (int j = 0; j < 8; j++) {
        float a = pv;
        float b = pv * r;
        pv = b * r;
        __nv_bfloat16 ha = __float2bfloat16(a), hb = __float2bfloat16(b);
        float la = a - __bfloat162float(ha);
        float lb = b - __bfloat162float(hb);
        __nv_bfloat16 lla = __float2bfloat16(la), llb = __float2bfloat16(lb);
        hh[j] = (unsigned)__bfloat16_as_ushort(ha) | ((unsigned)__bfloat16_as_ushort(hb) << 16);
        ll[j] = (unsigned)__bfloat16_as_ushort(lla) | ((unsigned)__bfloat16_as_ushort(llb) << 16);
    }
    uint4* pH = reinterpret_cast<uint4*>(Ah) + (size_t)idx * 2;
    uint4* pL = reinterpret_cast<uint4*>(Al) + (size_t)idx * 2;
    pH[0] = make_uint4(hh[0], hh[1], hh[2], hh[3]);
    pH[1] = make_uint4(hh[4], hh[5], hh[6], hh[7]);
    pL[0] = make_uint4(ll[0], ll[1], ll[2], ll[3]);
    pL[1] = make_uint4(ll[4], ll[5], ll[6], ll[7]);
}

// ---------------- coeff split (fold Kn; bf16 hi/lo; layout [o][k]) -------------
__global__ void k_coeff_split(const float* __restrict__ src, int K,
                              __nv_bfloat16* __restrict__ Bh, __nv_bfloat16* __restrict__ Bl) {
    int o = blockIdx.x;
    for (int k = threadIdx.x; k < K; k += blockDim.x) {
        int n = k & 15;
        float cn = fmaf((float)n, 4.f / 15.f, -2.f);
        float Kn = expf(-2.f * cn * cn);
        float v = src[(size_t)o * K + k] * Kn;
        __nv_bfloat16 h = __float2bfloat16(v);
        float lo = v - __bfloat162float(h);
        Bh[(size_t)o * K + k] = h;
        Bl[(size_t)o * K + k] = __float2bfloat16(lo);
    }
}

// ---------------- split-bf16 GEMM via mma.sync + fused tanh --------------------
__device__ __forceinline__ void load_tiles(uint32_t st,
        const __nv_bfloat16* __restrict__ Ah, const __nv_bfloat16* __restrict__ Al,
        const __nv_bfloat16* __restrict__ Bh, const __nv_bfloat16* __restrict__ Bl,
        int bm0, int on0, int k0, int K, int tid) {
#pragma unroll
    for (int q = 0; q < 4; q++) {
        int e = tid + (q << 8);           // 0..1023: 128 rows x 8 16B-chunks
        int row = e >> 3, ch = e & 7;
        uint32_t so = sw128((uint32_t)(row << 7) + (ch << 4));
        size_t ga = (size_t)(bm0 + row) * K + k0 + (ch << 3);
        size_t gb = (size_t)(on0 + row) * K + k0 + (ch << 3);
        cp16(st + ST_AH + so, Ah + ga);
        cp16(st + ST_AL + so, Al + ga);
        cp16(st + ST_BH + so, Bh + gb);
        cp16(st + ST_BL + so, Bl + gb);
    }
}

__global__ void __launch_bounds__(256, 1)
k_gemm(const __nv_bfloat16* __restrict__ Ah, const __nv_bfloat16* __restrict__ Al,
       const __nv_bfloat16* __restrict__ Bh, const __nv_bfloat16* __restrict__ Bl,
       float* __restrict__ out, int K) {
    extern __shared__ __align__(1024) char smem_raw[];
    const uint32_t base = smem_u32(smem_raw);
    const int tid = threadIdx.x;
    const int lane = tid & 31, wid = tid >> 5;
    const int wr = wid & 1, wc = wid >> 1;     // 2x4 warp grid: 64x32 per warp
    const int bm0 = blockIdx.y << 7, on0 = blockIdx.x << 7;
    const int NCH = K >> 6;

    float acc[4][4][4];
#pragma unroll
    for (int mt = 0; mt < 4; mt++)
#pragma unroll
        for (int nt = 0; nt < 4; nt++)
#pragma unroll
            for (int e = 0; e < 4; e++) acc[mt][nt][e] = 0.f;

    // ring: chunk c lives in buffer (c % 3)
    load_tiles(base, Ah, Al, Bh, Bl, bm0, on0, 0, K, tid);
    CP_COMMIT();
    load_tiles(base + STAGE_BYTES, Ah, Al, Bh, Bl, bm0, on0, BK, K, tid);
    CP_COMMIT();

    const int g = lane >> 3, lr = lane & 7;
    for (int c = 0; c < NCH; c++) {
        if (c == NCH - 1) asm volatile("cp.async.wait_group 0;" ::: "memory");
        else              asm volatile("cp.async.wait_group 1;" ::: "memory");
        __syncthreads();

        // prefetch chunk c+2 into buffer (c+2)%3 (free: consumed at iter c-1,
        // and everyone passed this iteration's barrier)
        if (c + 2 < NCH) {
            uint32_t nb = (uint32_t)((c + 2) % 3);
            load_tiles(base + nb * STAGE_BYTES, Ah, Al, Bh, Bl,
                       bm0, on0, (c + 2) << 6, K, tid);
            CP_COMMIT();
        }

        uint32_t st = base + (uint32_t)(c % 3) * STAGE_BYTES;

#pragma unroll
        for (int kk = 0; kk < 4; kk++) {
            uint32_t afh[4][4], afl[4][4];
#pragma unroll
            for (int mt = 0; mt < 4; mt++) {
                int m_local = wr * 64 + mt * 16 + (g & 1) * 8 + lr;
                uint32_t off = sw128((uint32_t)(m_local << 7) + (kk << 5) + ((g >> 1) << 4));
                ldmx4(afh[mt], st + ST_AH + off);
                ldmx4(afl[mt], st + ST_AL + off);
            }
            uint32_t bfh[2][4], bfl[2][4];
#pragma unroll
            for (int n2 = 0; n2 < 2; n2++) {
                int n_local = wc * 32 + n2 * 16 + (g >> 1) * 8 + lr;
                uint32_t off = sw128((uint32_t)(n_local << 7) + (kk << 5) + ((g & 1) << 4));
                ldmx4(bfh[n2], st + ST_BH + off);
                ldmx4(bfl[n2], st + ST_BL + off);
            }
#pragma unroll
            for (int mt = 0; mt < 4; mt++)
#pragma unroll
                for (int nt = 0; nt < 4; nt++) {
                    const uint32_t* B0 = &bfh[nt >> 1][(nt & 1) * 2];
                    const uint32_t* B1 = &bfl[nt >> 1][(nt & 1) * 2];
                    mma16816(acc[mt][nt], afh[mt], B0);
                    mma16816(acc[mt][nt], afh[mt], B1);
                    mma16816(acc[mt][nt], afl[mt], B0);
                }
        }
    }

    // epilogue: tanh + store (C frag: lane l -> rows l/4, l/4+8; cols 2*(l%4)+{0,1})
#pragma unroll
    for (int mt = 0; mt < 4; mt++) {
        int row0 = bm0 + wr * 64 + mt * 16 + (lane >> 2);
#pragma unroll
        for (int nt = 0; nt < 4; nt++) {
            int col = on0 + wc * 32 + nt * 8 + (lane & 3) * 2;
            float2 v0, v1;
            v0.x = tanhf(acc[mt][nt][0]);
            v0.y = tanhf(acc[mt][nt][1]);
            v1.x = tanhf(acc[mt][nt][2]);
            v1.y = tanhf(acc[mt][nt][3]);
            *reinterpret_cast<float2*>(out + (size_t)row0 * HD + col) = v0;
            *reinterpret_cast<float2*>(out + (size_t)(row0 + 8) * HD + col) = v1;
        }
    }
}

// ---------------- layer-3 path (SIMT, tiny) -------------------------------------
__global__ void k_prep_tr(const float* __restrict__ src, const float* __restrict__ mu,
                          const float* __restrict__ inv, int cmask, int total,
                          float2* __restrict__ dst) {
    for (int idx = blockIdx.x * blockDim.x + threadIdx.x; idx < total;
         idx += gridDim.x * blockDim.x) {
        int c = idx & cmask;
        float xn = (src[idx] - mu[c]) * inv[c];
        xn = fminf(3.f, fmaxf(-3.f, xn));
        float t = __expf(fmaf(-2.f * xn, xn, -8.f * xn));
        float r = __expf(xn * (16.f / 15.f));
        dst[idx] = make_float2(t, r);
    }
}

__global__ void k_prep_coeffs3(const float* __restrict__ src, float* __restrict__ dst) {
    int i = blockIdx.x;
    for (int j = threadIdx.x; j < NB; j += blockDim.x) {
        int n = 15 - j;   // Horner order
        float cn = fmaf((float)n, 4.f / 15.f, -2.f);
        float Kn = expf(-2.f * cn * cn);
        dst[i * NB + j] = src[(size_t)i * NB + n] * Kn;
    }
}

__global__ void k_final(const float2* __restrict__ tr, const float* __restrict__ cp3,
                        const float* __restrict__ x, const float* __restrict__ sw,
                        const float* __restrict__ sb, float* __restrict__ out) {
    int warp = threadIdx.x >> 5, lane = threadIdx.x & 31;
    int b = blockIdx.x * 8 + warp;
    float acc = 0.f;
    for (int i = lane; i < HD; i += 32) {
        float2 v = tr[(size_t)b * HD + i];
        const float* c = &cp3[i * NB];
        float p = c[0];
#pragma unroll
        for (int j = 1; j < NB; j++) p = fmaf(p, v.y, c[j]);
        acc = fmaf(v.x, p, acc);
    }
    for (int cidx = lane; cidx < IN1; cidx += 32)
        acc = fmaf(x[(size_t)b * IN1 + cidx], sw[cidx], acc);
#pragma unroll
    for (int off = 16; off; off >>= 1) acc += __shfl_xor_sync(0xffffffffu, acc, off);
    if (lane == 0) out[b] = acc + sb[0];
}

// ---------------- launch ---------------------------------------------------------
extern "C" void kernel_launch(void* const* d_in, const int* in_sizes, int n_in,
                              void* d_out, int out_size) {
    const float* x  = (const float*)d_in[0];
    const float* c1 = (const float*)d_in[1];
    const float* c2 = (const float*)d_in[2];
    const float* c3 = (const float*)d_in[3];
    const float* sw = (const float*)d_in[4];
    const float* sb = (const float*)d_in[5];
    float* out = (float*)d_out;

    __nv_bfloat16 *Ah, *Al, *cb1h, *cb1l, *cb2h, *cb2l;
    float *h1, *h2, *cp3, *mu1, *inv1, *mu2, *inv2, *mu3, *inv3;
    float2* tr;
    cudaGetSymbolAddress((void**)&Ah,   g_Ah);
    cudaGetSymbolAddress((void**)&Al,   g_Al);
    cudaGetSymbolAddress((void**)&cb1h, g_cb1h);
    cudaGetSymbolAddress((void**)&cb1l, g_cb1l);
    cudaGetSymbolAddress((void**)&cb2h, g_cb2h);
    cudaGetSymbolAddress((void**)&cb2l, g_cb2l);
    cudaGetSymbolAddress((void**)&h1,   g_h1);
    cudaGetSymbolAddress((void**)&h2,   g_h2);
    cudaGetSymbolAddress((void**)&cp3,  g_cp3);
    cudaGetSymbolAddress((void**)&tr,   g_tr);
    cudaGetSymbolAddress((void**)&mu1,  g_mu1);
    cudaGetSymbolAddress((void**)&inv1, g_inv1);
    cudaGetSymbolAddress((void**)&mu2,  g_mu2);
    cudaGetSymbolAddress((void**)&inv2, g_inv2);
    cudaGetSymbolAddress((void**)&mu3,  g_mu3);
    cudaGetSymbolAddress((void**)&inv3, g_inv3);

    cudaFuncSetAttribute(k_gemm, cudaFuncAttributeMaxDynamicSharedMemorySize, GEMM_SMEM);

    // coeff prep
    k_coeff_split<<<HD, 256>>>(c1, K1, cb1h, cb1l);
    k_coeff_split<<<HD, 256>>>(c2, K2, cb2h, cb2l);
    k_prep_coeffs3<<<HD, 32>>>(c3, cp3);

    // layer 1
    k_stats_part<<<NPART, 256>>>(x, IN1);
    k_stats_fin<<<1, 256>>>(IN1, mu1, inv1);
    k_basis<<<(B_ROWS * IN1) / 256, 256>>>(x, mu1, inv1, IN1 - 1, Ah, Al);
    k_gemm<<<dim3(HD / BN, B_ROWS / BM), 256, GEMM_SMEM>>>(Ah, Al, cb1h, cb1l, h1, K1);

    // layer 2
    k_stats_part<<<NPART, 256>>>(h1, HD);
    k_stats_fin<<<2, 256>>>(HD, mu2, inv2);
    k_basis<<<(B_ROWS * HD) / 256, 256>>>(h1, mu2, inv2, HD - 1, Ah, Al);
    k_gemm<<<dim3(HD / BN, B_ROWS / BM), 256, GEMM_SMEM>>>(Ah, Al, cb2h, cb2l, h2, K2);

    // layer 3 + skip
    k_stats_part<<<NPART, 256>>>(h2, HD);
    k_stats_fin<<<2, 256>>>(HD, mu3, inv3);
    k_prep_tr<<<4096, 256>>>(h2, mu3, inv3, HD - 1, B_ROWS * HD, tr);
    k_final<<<B_ROWS / 8, 256>>>(tr, cp3, x, sw, sb, out);
}